// round 2
// baseline (speedup 1.0000x reference)
#include <cuda_runtime.h>
#include <math.h>

#define TT   1024
#define BATCH 64
#define DIN  256
#define DH   256
#define NG   1024           // 4 gates * DH

// ---------------- scratch (device globals: no allocation allowed) ----------
__device__ float g_P[(size_t)TT * BATCH * NG];   // precomputed x-projection + bias, 256 MB
__device__ float g_h[2 * BATCH * DH];            // double-buffered hidden state
__device__ unsigned g_bar_count = 0;
__device__ unsigned g_bar_gen   = 0;

// ---------------- phase 1: P[t*B+b, gate*256+j] = X row @ Wx_gate + bias ---
// M=65536, N=1024, K=256 classic SGEMM, 128x128 tile, 8x8 per thread.
__global__ __launch_bounds__(256, 2)
void gemm_x_kernel(const float* __restrict__ X,
                   const float* __restrict__ Wf, const float* __restrict__ Wi,
                   const float* __restrict__ Wg, const float* __restrict__ Wo,
                   const float* __restrict__ bf, const float* __restrict__ bi,
                   const float* __restrict__ bg, const float* __restrict__ bo)
{
    const int BM = 128, BN = 128, BK = 8;
    __shared__ float As[BK][BM];
    __shared__ float Bs[BK][BN];

    int tid = threadIdx.x;
    int n0  = blockIdx.x * BN;       // global gate-column base (0..1023), within one gate
    int m0  = blockIdx.y * BM;       // row base in [0, 65536)

    int gate = n0 >> 8;
    const float* W    = (gate == 0) ? Wf : (gate == 1) ? Wi : (gate == 2) ? Wg : Wo;
    const float* bias = (gate == 0) ? bf : (gate == 1) ? bi : (gate == 2) ? bg : bo;
    int ncol0 = n0 & 255;            // column offset inside this gate's W

    int tx = tid & 15;               // 16 col-groups
    int ty = tid >> 4;               // 16 row-groups

    float acc[8][8];
#pragma unroll
    for (int i = 0; i < 8; i++)
#pragma unroll
        for (int j = 0; j < 8; j++) acc[i][j] = 0.f;

    int arow = tid >> 1, ak = (tid & 1) * 4;     // A tile load mapping
    int brow = tid >> 5, bc = (tid & 31) * 4;    // B tile load mapping

    for (int kt = 0; kt < DIN; kt += BK) {
        float4 av = *(const float4*)(X + (size_t)(m0 + arow) * DIN + kt + ak);
        float4 bv = *(const float4*)(W + (size_t)(kt + brow) * DH + ncol0 + bc);
        As[ak + 0][arow] = av.x;
        As[ak + 1][arow] = av.y;
        As[ak + 2][arow] = av.z;
        As[ak + 3][arow] = av.w;
        *(float4*)&Bs[brow][bc] = bv;
        __syncthreads();

#pragma unroll
        for (int k = 0; k < BK; k++) {
            float ra[8], rb[8];
            *(float4*)&ra[0] = *(const float4*)&As[k][ty * 4];
            *(float4*)&ra[4] = *(const float4*)&As[k][64 + ty * 4];
            *(float4*)&rb[0] = *(const float4*)&Bs[k][tx * 4];
            *(float4*)&rb[4] = *(const float4*)&Bs[k][64 + tx * 4];
#pragma unroll
            for (int i = 0; i < 8; i++)
#pragma unroll
                for (int j = 0; j < 8; j++)
                    acc[i][j] = fmaf(ra[i], rb[j], acc[i][j]);
        }
        __syncthreads();
    }

    // epilogue: add bias, store to g_P
    float bv[8];
#pragma unroll
    for (int j = 0; j < 4; j++) {
        bv[j]     = bias[ncol0 + tx * 4 + j];
        bv[4 + j] = bias[ncol0 + 64 + tx * 4 + j];
    }
#pragma unroll
    for (int i = 0; i < 8; i++) {
        int r = (i < 4) ? (ty * 4 + i) : (64 + ty * 4 + (i - 4));
        float4 o0 = {acc[i][0] + bv[0], acc[i][1] + bv[1],
                     acc[i][2] + bv[2], acc[i][3] + bv[3]};
        float4 o1 = {acc[i][4] + bv[4], acc[i][5] + bv[5],
                     acc[i][6] + bv[6], acc[i][7] + bv[7]};
        float* dst = g_P + (size_t)(m0 + r) * NG + n0;
        *(float4*)(dst + tx * 4)      = o0;
        *(float4*)(dst + 64 + tx * 4) = o1;
    }
}

// ---------------- phase 2: persistent recurrent kernel ---------------------
#define PD     8            // d_h partitions (32 d_h cols each)
#define PB     16           // batch partitions (4 rows each)
#define NCTA   (PD * PB)    // 128 CTAs, all co-resident (1/SM)
#define NTHR   256
#define WPAD   260          // Wh smem row stride (floats): 16B-aligned + conflict-free

struct S2 {
    float Wh[128][WPAD];     // [gatecol][k]  (130 KB, resident all steps)
    float hs[4][DH];         // this CTA's 4 batch rows of h(t)
    float gbuf[4][4][32];    // [gate][row][j] pre-activation exchange
};

__device__ __forceinline__ float sigmoidf(float x) { return 1.f / (1.f + expf(-x)); }

__device__ __forceinline__ void grid_barrier()
{
    __syncthreads();
    if (threadIdx.x == 0) {
        volatile unsigned* genp = &g_bar_gen;
        unsigned my = *genp;                 // read gen BEFORE arriving
        __threadfence();
        unsigned arr = atomicAdd(&g_bar_count, 1);
        if (arr == NCTA - 1) {
            g_bar_count = 0;                 // all arrived; safe to reset
            __threadfence();
            atomicAdd(&g_bar_gen, 1);        // release
        } else {
            while (*genp == my) { }          // spin on L2 line
        }
        __threadfence();
    }
    __syncthreads();
}

extern __shared__ char smem_raw[];

__global__ __launch_bounds__(NTHR, 1)
void lstm_rec_kernel(const float* __restrict__ Wf, const float* __restrict__ Wi,
                     const float* __restrict__ Wg, const float* __restrict__ Wo,
                     float* __restrict__ out, int out_size)
{
    S2* s = (S2*)smem_raw;
    int tid = threadIdx.x;
    int dg = blockIdx.x & (PD - 1);      // d_h group
    int bg = blockIdx.x / PD;            // batch group
    int d0 = dg * 32;
    int b0 = bg * 4;

    // ---- load this CTA's Wh slice (h-part rows of W, cols d0..d0+31, all 4 gates)
    for (int idx = tid; idx < 128 * 256; idx += NTHR) {
        int c  = idx & 127;              // gate-col 0..127
        int kk = idx >> 7;               // k 0..255
        int gate = c >> 5;
        int j = d0 + (c & 31);
        const float* W = (gate == 0) ? Wf : (gate == 1) ? Wi : (gate == 2) ? Wg : Wo;
        s->Wh[c][kk] = W[(size_t)(DIN + kk) * DH + j];
    }

    // ---- zero our read-slice of h buffer 0 (redundant same-value writes across dg: fine)
    {
        float4 z = {0.f, 0.f, 0.f, 0.f};
        int rr = tid >> 6, k4 = (tid & 63) * 4;
        *(float4*)&g_h[(size_t)(b0 + rr) * DH + k4] = z;
    }

    int r  = tid >> 6;                   // batch row 0..3
    int c0 = tid & 63;                   // columns c0 and c0+64
    const float* w0 = s->Wh[c0];
    const float* w1 = s->Wh[c0 + 64];
    int gate0 = c0 >> 5;                 // 0 or 1  (pair gate: gate0+2)
    int jj = c0 & 31;
    int gcol0 = (gate0 << 8) + d0 + jj;          // global gate-col of acc0
    int gcol1 = ((gate0 + 2) << 8) + d0 + jj;    // global gate-col of acc1

    float c_reg = 0.f;                   // cell state, owned by tid<128

    const size_t HOFF = (size_t)TT * BATCH * DH;

    for (int t = 0; t < TT; t++) {
        // load h(t) slice -> smem, and prefetch P (used only after k-loop)
        {
            int rr = tid >> 6, k4 = (tid & 63) * 4;
            float4 hv = *(const float4*)&g_h[(size_t)((t & 1) * BATCH + b0 + rr) * DH + k4];
            *(float4*)&s->hs[rr][k4] = hv;
        }
        const float* Pt = g_P + ((size_t)t * BATCH + b0 + r) * NG;
        float p0 = __ldcs(Pt + gcol0);
        float p1 = __ldcs(Pt + gcol1);
        __syncthreads();

        float a0 = 0.f, a1 = 0.f, a2 = 0.f, a3 = 0.f;
        const float* hrow = s->hs[r];
#pragma unroll 8
        for (int kk = 0; kk < DH; kk += 4) {
            float4 h4 = *(const float4*)(hrow + kk);
            float4 wa = *(const float4*)(w0 + kk);
            float4 wb = *(const float4*)(w1 + kk);
            a0 = fmaf(h4.x, wa.x, a0); a2 = fmaf(h4.y, wa.y, a2);
            a0 = fmaf(h4.z, wa.z, a0); a2 = fmaf(h4.w, wa.w, a2);
            a1 = fmaf(h4.x, wb.x, a1); a3 = fmaf(h4.y, wb.y, a3);
            a1 = fmaf(h4.z, wb.z, a1); a3 = fmaf(h4.w, wb.w, a3);
        }
        float gv0 = (a0 + a2) + p0;
        float gv1 = (a1 + a3) + p1;
        s->gbuf[gate0][r][jj]     = gv0;
        s->gbuf[gate0 + 2][r][jj] = gv1;
        __syncthreads();

        if (tid < 128) {
            int r2 = tid >> 5, j2 = tid & 31;
            float f  = sigmoidf(s->gbuf[0][r2][j2]);
            float i_ = sigmoidf(s->gbuf[1][r2][j2]);
            float g_ = tanhf   (s->gbuf[2][r2][j2]);
            float o_ = sigmoidf(s->gbuf[3][r2][j2]);
            c_reg = f * c_reg + i_ * g_;
            float hvn = o_ * tanhf(c_reg);
            int b = b0 + r2, d = d0 + j2;
            g_h[(size_t)(((t + 1) & 1) * BATCH + b) * DH + d] = hvn;
            out[(size_t)((size_t)t * BATCH + b) * DH + d] = hvn;
            if (t == TT - 1) {
                if (HOFF + (size_t)2 * BATCH * DH <= (size_t)out_size) {
                    out[HOFF + (size_t)b * DH + d] = hvn;                       // hT
                    out[HOFF + (size_t)BATCH * DH + (size_t)b * DH + d] = c_reg; // cT
                }
            }
        }
        __threadfence();     // make g_h writes visible before barrier release
        grid_barrier();
    }
}

// ---------------- launch ---------------------------------------------------
extern "C" void kernel_launch(void* const* d_in, const int* in_sizes, int n_in,
                              void* d_out, int out_size)
{
    const float* X  = (const float*)d_in[0];
    const float* Wf = (const float*)d_in[1];
    const float* bf = (const float*)d_in[2];
    const float* Wi = (const float*)d_in[3];
    const float* bi = (const float*)d_in[4];
    const float* Wg = (const float*)d_in[5];
    const float* bg = (const float*)d_in[6];
    const float* Wo = (const float*)d_in[7];
    const float* bo = (const float*)d_in[8];
    float* out = (float*)d_out;

    // phase 1: big parallel GEMM for the x-projection of all timesteps
    dim3 g1(NG / 128, (TT * BATCH) / 128);
    gemm_x_kernel<<<g1, 256>>>(X, Wf, Wi, Wg, Wo, bf, bi, bg, bo);

    // phase 2: persistent recurrent kernel (128 co-resident CTAs, grid barrier/step)
    cudaFuncSetAttribute(lstm_rec_kernel,
                         cudaFuncAttributeMaxDynamicSharedMemorySize,
                         (int)sizeof(S2));
    lstm_rec_kernel<<<NCTA, NTHR, sizeof(S2)>>>(Wf, Wi, Wg, Wo, out, out_size);
}

// round 4
// speedup vs baseline: 1.0961x; 1.0961x over previous
#include <cuda_runtime.h>
#include <math.h>
#include <stdint.h>

#define TT    1024
#define BATCH 64
#define DIN   256
#define DH    256
#define NG    1024           // 4 gates * DH

// ---------------- scratch (device globals: no allocation allowed) ----------
__device__ float g_P[(size_t)TT * BATCH * NG];   // precomputed x-projection + bias, 256 MB

// ---------------- phase 1: P[t*B+b, gate*256+j] = X row @ Wx_gate + bias ---
// M=65536, N=1024, K=256 classic SGEMM, 128x128 tile, 8x8 per thread.
__global__ __launch_bounds__(256, 2)
void gemm_x_kernel(const float* __restrict__ X,
                   const float* __restrict__ Wf, const float* __restrict__ Wi,
                   const float* __restrict__ Wg, const float* __restrict__ Wo,
                   const float* __restrict__ bf, const float* __restrict__ bi,
                   const float* __restrict__ bg, const float* __restrict__ bo)
{
    const int BM = 128, BN = 128, BK = 8;
    __shared__ float As[BK][BM];
    __shared__ float Bs[BK][BN];

    int tid = threadIdx.x;
    int n0  = blockIdx.x * BN;       // global gate-column base (0..1023)
    int m0  = blockIdx.y * BM;       // row base in [0, 65536)

    int gate = n0 >> 8;
    const float* W    = (gate == 0) ? Wf : (gate == 1) ? Wi : (gate == 2) ? Wg : Wo;
    const float* bias = (gate == 0) ? bf : (gate == 1) ? bi : (gate == 2) ? bg : bo;
    int ncol0 = n0 & 255;

    int tx = tid & 15;
    int ty = tid >> 4;

    float acc[8][8];
#pragma unroll
    for (int i = 0; i < 8; i++)
#pragma unroll
        for (int j = 0; j < 8; j++) acc[i][j] = 0.f;

    int arow = tid >> 1, ak = (tid & 1) * 4;
    int brow = tid >> 5, bc = (tid & 31) * 4;

    for (int kt = 0; kt < DIN; kt += BK) {
        float4 av = *(const float4*)(X + (size_t)(m0 + arow) * DIN + kt + ak);
        float4 bv = *(const float4*)(W + (size_t)(kt + brow) * DH + ncol0 + bc);
        As[ak + 0][arow] = av.x;
        As[ak + 1][arow] = av.y;
        As[ak + 2][arow] = av.z;
        As[ak + 3][arow] = av.w;
        *(float4*)&Bs[brow][bc] = bv;
        __syncthreads();

#pragma unroll
        for (int k = 0; k < BK; k++) {
            float ra[8], rb[8];
            *(float4*)&ra[0] = *(const float4*)&As[k][ty * 4];
            *(float4*)&ra[4] = *(const float4*)&As[k][64 + ty * 4];
            *(float4*)&rb[0] = *(const float4*)&Bs[k][tx * 4];
            *(float4*)&rb[4] = *(const float4*)&Bs[k][64 + tx * 4];
#pragma unroll
            for (int i = 0; i < 8; i++)
#pragma unroll
                for (int j = 0; j < 8; j++)
                    acc[i][j] = fmaf(ra[i], rb[j], acc[i][j]);
        }
        __syncthreads();
    }

    float bv[8];
#pragma unroll
    for (int j = 0; j < 4; j++) {
        bv[j]     = bias[ncol0 + tx * 4 + j];
        bv[4 + j] = bias[ncol0 + 64 + tx * 4 + j];
    }
#pragma unroll
    for (int i = 0; i < 8; i++) {
        int r = (i < 4) ? (ty * 4 + i) : (64 + ty * 4 + (i - 4));
        float4 o0 = {acc[i][0] + bv[0], acc[i][1] + bv[1],
                     acc[i][2] + bv[2], acc[i][3] + bv[3]};
        float4 o1 = {acc[i][4] + bv[4], acc[i][5] + bv[5],
                     acc[i][6] + bv[6], acc[i][7] + bv[7]};
        float* dst = g_P + (size_t)(m0 + r) * NG + n0;
        *(float4*)(dst + tx * 4)      = o0;
        *(float4*)(dst + 64 + tx * 4) = o1;
    }
}

// ---------------- phase 2: clustered persistent recurrent kernel -----------
// 16 independent clusters (one per 4-row batch group), 8 CTAs/cluster (d_h split).
// h(t) exchanged via DSMEM remote stores + barrier.cluster — no global sync.
#define CLUSTER 8
#define NCLUS   (BATCH / 4)     // 16
#define NCTA2   (CLUSTER * NCLUS)
#define NTHR2   128
#define WPAD    260             // float stride: 16B-aligned, phase-conflict-free

struct S2 {
    float Wh[128][WPAD];        // [gatecol][k]  ~130 KB, resident all steps
    float hs[2][4][DH];         // double-buffered h(t): [buf][row][dcol 0..255]
    float gbuf[4][4][32];       // [gate][row][j] pre-activation exchange
};

#define FMA2(acc, a, b) \
    asm("fma.rn.f32x2 %0, %1, %2, %0;" : "+l"(acc) : "l"(a), "l"(b))

__device__ __forceinline__ float pairsum(unsigned long long v) {
    float lo = __uint_as_float((unsigned)(v & 0xffffffffull));
    float hi = __uint_as_float((unsigned)(v >> 32));
    return lo + hi;
}
__device__ __forceinline__ float fsig(float x) {
    return __fdividef(1.f, 1.f + __expf(-x));
}
__device__ __forceinline__ float ftanh(float x) {
    return __fdividef(2.f, 1.f + __expf(-2.f * x)) - 1.f;
}

extern __shared__ char smem_raw[];

__global__ __launch_bounds__(NTHR2, 1) __cluster_dims__(CLUSTER, 1, 1)
void lstm_rec_kernel(const float* __restrict__ Wf, const float* __restrict__ Wi,
                     const float* __restrict__ Wg, const float* __restrict__ Wo,
                     float* __restrict__ out, int out_size)
{
    S2* s = (S2*)smem_raw;
    int tid = threadIdx.x;
    uint32_t rank;
    asm("mov.u32 %0, %%cluster_ctarank;" : "=r"(rank));
    int d0 = (int)rank * 32;                 // my 32 d_h columns
    int b0 = (blockIdx.x >> 3) * 4;          // my 4 batch rows

    // ---- load this CTA's Wh slice: h-part rows of W, 4 gates x 32 cols
    for (int idx = tid; idx < 128 * 256; idx += NTHR2) {
        int c  = idx & 127;                  // gate-col 0..127
        int kk = idx >> 7;                   // k 0..255
        int gate = c >> 5;
        int j = d0 + (c & 31);
        const float* W = (gate == 0) ? Wf : (gate == 1) ? Wi : (gate == 2) ? Wg : Wo;
        s->Wh[c][kk] = W[(size_t)(DIN + kk) * DH + j];
    }
    // ---- zero local h buffer 0 (h(0) = 0)
    for (int idx = tid; idx < 4 * DH / 4; idx += NTHR2)
        ((float4*)s->hs[0])[idx] = make_float4(0.f, 0.f, 0.f, 0.f);
    __syncthreads();
    asm volatile("barrier.cluster.arrive.aligned;" ::: "memory");
    asm volatile("barrier.cluster.wait.aligned;"   ::: "memory");

    // ---- roles
    int c0 = tid & 63;                       // cols c0 and c0+64
    int rp = tid >> 6;                       // rows rp and rp+2
    const float* w0 = s->Wh[c0];
    const float* w1 = s->Wh[c0 + 64];
    int g0 = c0 >> 5, jj = c0 & 31;
    int gcol0 = (g0 << 8) + d0 + jj;         // global gate-col of col pair 0
    int gcol1 = ((g0 + 2) << 8) + d0 + jj;

    int r2 = tid >> 5, j2 = tid & 31;        // activation role: (row r2, dcol d0+j2)
    float c_reg = 0.f;

    // precompute remote DSMEM addresses of my activation slot in both buffers
    uint32_t hsa0 = (uint32_t)__cvta_generic_to_shared(&s->hs[0][r2][d0 + j2]);
    uint32_t hsa1 = (uint32_t)__cvta_generic_to_shared(&s->hs[1][r2][d0 + j2]);
    uint32_t ra0[CLUSTER], ra1[CLUSTER];
#pragma unroll
    for (int p = 0; p < CLUSTER; p++) {
        asm("mapa.shared::cluster.u32 %0, %1, %2;" : "=r"(ra0[p]) : "r"(hsa0), "r"(p));
        asm("mapa.shared::cluster.u32 %0, %1, %2;" : "=r"(ra1[p]) : "r"(hsa1), "r"(p));
    }

    // P row pointers (advance by BATCH*NG per step)
    const float* pA = g_P + (size_t)(b0 + rp) * NG;
    const float* pB = g_P + (size_t)(b0 + rp + 2) * NG;
    float p00 = __ldcs(pA + gcol0), p01 = __ldcs(pA + gcol1);
    float p10 = __ldcs(pB + gcol0), p11 = __ldcs(pB + gcol1);

    float* orow = out + (size_t)(b0 + r2) * DH + d0 + j2;
    const size_t HOFF = (size_t)TT * BATCH * DH;

    for (int t = 0; t < TT; t++) {
        const ulonglong2* hAp = (const ulonglong2*)s->hs[t & 1][rp];
        const ulonglong2* hBp = (const ulonglong2*)s->hs[t & 1][rp + 2];
        const ulonglong2* wAp = (const ulonglong2*)w0;
        const ulonglong2* wBp = (const ulonglong2*)w1;

        unsigned long long aA0x = 0, aA0y = 0, aA1x = 0, aA1y = 0;
        unsigned long long aB0x = 0, aB0y = 0, aB1x = 0, aB1y = 0;
#pragma unroll 8
        for (int i = 0; i < DH / 4; i++) {
            ulonglong2 wa = wAp[i];
            ulonglong2 wb = wBp[i];
            ulonglong2 ha = hAp[i];
            ulonglong2 hb = hBp[i];
            FMA2(aA0x, ha.x, wa.x); FMA2(aA0y, ha.y, wa.y);
            FMA2(aA1x, ha.x, wb.x); FMA2(aA1y, ha.y, wb.y);
            FMA2(aB0x, hb.x, wa.x); FMA2(aB0y, hb.y, wa.y);
            FMA2(aB1x, hb.x, wb.x); FMA2(aB1y, hb.y, wb.y);
        }
        float gv00 = (pairsum(aA0x) + pairsum(aA0y)) + p00;
        float gv01 = (pairsum(aA1x) + pairsum(aA1y)) + p01;
        float gv10 = (pairsum(aB0x) + pairsum(aB0y)) + p10;
        float gv11 = (pairsum(aB1x) + pairsum(aB1y)) + p11;

        s->gbuf[g0][rp][jj]         = gv00;
        s->gbuf[g0 + 2][rp][jj]     = gv01;
        s->gbuf[g0][rp + 2][jj]     = gv10;
        s->gbuf[g0 + 2][rp + 2][jj] = gv11;
        __syncthreads();

        // activation: every thread owns one (row, dcol) cell
        float f  = fsig (s->gbuf[0][r2][j2]);
        float i_ = fsig (s->gbuf[1][r2][j2]);
        float g_ = ftanh(s->gbuf[2][r2][j2]);
        float o_ = fsig (s->gbuf[3][r2][j2]);
        c_reg = f * c_reg + i_ * g_;
        float hvn = o_ * ftanh(c_reg);

        orow[(size_t)t * BATCH * DH] = hvn;
        if (t == TT - 1 &&
            HOFF + (size_t)2 * BATCH * DH <= (size_t)out_size) {
            out[HOFF + (size_t)(b0 + r2) * DH + d0 + j2] = hvn;
            out[HOFF + (size_t)BATCH * DH + (size_t)(b0 + r2) * DH + d0 + j2] = c_reg;
        }

        // broadcast h(t+1)[r2][d0+j2] into every cluster CTA's hs[(t+1)&1]
        const uint32_t* ra = (t & 1) ? ra0 : ra1;
#pragma unroll
        for (int p = 0; p < CLUSTER; p++)
            asm volatile("st.shared::cluster.f32 [%0], %1;"
                         :: "r"(ra[p]), "f"(hvn) : "memory");

        // prefetch next-step P (DRAM latency hides under the cluster barrier)
        pA += (size_t)BATCH * NG;
        pB += (size_t)BATCH * NG;
        if (t + 1 < TT) {
            p00 = __ldcs(pA + gcol0); p01 = __ldcs(pA + gcol1);
            p10 = __ldcs(pB + gcol0); p11 = __ldcs(pB + gcol1);
        }

        asm volatile("barrier.cluster.arrive.aligned;" ::: "memory");
        asm volatile("barrier.cluster.wait.aligned;"   ::: "memory");
    }
}

// ---------------- launch ---------------------------------------------------
extern "C" void kernel_launch(void* const* d_in, const int* in_sizes, int n_in,
                              void* d_out, int out_size)
{
    const float* X  = (const float*)d_in[0];
    const float* Wf = (const float*)d_in[1];
    const float* bf = (const float*)d_in[2];
    const float* Wi = (const float*)d_in[3];
    const float* bi = (const float*)d_in[4];
    const float* Wg = (const float*)d_in[5];
    const float* bg = (const float*)d_in[6];
    const float* Wo = (const float*)d_in[7];
    const float* bo = (const float*)d_in[8];
    float* out = (float*)d_out;

    // phase 1: big parallel GEMM for the x-projection of all timesteps
    dim3 g1(NG / 128, (TT * BATCH) / 128);
    gemm_x_kernel<<<g1, 256>>>(X, Wf, Wi, Wg, Wo, bf, bi, bg, bo);

    // phase 2: 16 clusters x 8 CTAs, DSMEM h-exchange, no global barrier
    cudaFuncSetAttribute(lstm_rec_kernel,
                         cudaFuncAttributeMaxDynamicSharedMemorySize,
                         (int)sizeof(S2));
    lstm_rec_kernel<<<NCTA2, NTHR2, sizeof(S2)>>>(Wf, Wi, Wg, Wo, out, out_size);
}

// round 5
// speedup vs baseline: 1.2322x; 1.1242x over previous
#include <cuda_runtime.h>
#include <math.h>
#include <stdint.h>

#define TT    1024
#define BATCH 64
#define DIN   256
#define DH    256
#define NG    1024           // 4 gates * DH

// ---------------- scratch (device globals: no allocation allowed) ----------
__device__ float g_P[(size_t)TT * BATCH * NG];   // precomputed x-projection + bias, 256 MB

#define FMA2(acc, a, b) \
    asm("fma.rn.f32x2 %0, %1, %2, %0;" : "+l"(acc) : "l"(a), "l"(b))
#define PACKDUP(d, f) \
    asm("mov.b64 %0, {%1, %1};" : "=l"(d) : "f"(f))

__device__ __forceinline__ float pairsum(unsigned long long v) {
    float lo = __uint_as_float((unsigned)(v & 0xffffffffull));
    float hi = __uint_as_float((unsigned)(v >> 32));
    return lo + hi;
}
__device__ __forceinline__ float lo32(unsigned long long v) {
    return __uint_as_float((unsigned)(v & 0xffffffffull));
}
__device__ __forceinline__ float hi32(unsigned long long v) {
    return __uint_as_float((unsigned)(v >> 32));
}

// ---------------- phase 1: P[t*B+b, gate*256+j] = X row @ Wx_gate + bias ---
// M=65536, N=1024, K=256 SGEMM, 128x128 tile, 8x8 per thread, FFMA2 inner.
__global__ __launch_bounds__(256, 2)
void gemm_x_kernel(const float* __restrict__ X,
                   const float* __restrict__ Wf, const float* __restrict__ Wi,
                   const float* __restrict__ Wg, const float* __restrict__ Wo,
                   const float* __restrict__ bf, const float* __restrict__ bi,
                   const float* __restrict__ bg, const float* __restrict__ bo)
{
    const int BM = 128, BN = 128, BK = 8;
    __shared__ float As[BK][BM];
    __shared__ float Bs[BK][BN];

    int tid = threadIdx.x;
    int n0  = blockIdx.x * BN;       // gate-column base (0..1023)
    int m0  = blockIdx.y * BM;       // row base in [0, 65536)

    int gate = n0 >> 8;
    const float* W    = (gate == 0) ? Wf : (gate == 1) ? Wi : (gate == 2) ? Wg : Wo;
    const float* bias = (gate == 0) ? bf : (gate == 1) ? bi : (gate == 2) ? bg : bo;
    int ncol0 = n0 & 255;

    int tx = tid & 15;
    int ty = tid >> 4;

    // acc2[ip][j]: ip = row-pair index (rows in lo/hi halves), j = col 0..7
    unsigned long long acc2[4][8];
#pragma unroll
    for (int i = 0; i < 4; i++)
#pragma unroll
        for (int j = 0; j < 8; j++) acc2[i][j] = 0ull;

    int arow = tid >> 1, ak = (tid & 1) * 4;
    int brow = tid >> 5, bc = (tid & 31) * 4;

    for (int kt = 0; kt < DIN; kt += BK) {
        float4 av = *(const float4*)(X + (size_t)(m0 + arow) * DIN + kt + ak);
        float4 bv = *(const float4*)(W + (size_t)(kt + brow) * DH + ncol0 + bc);
        As[ak + 0][arow] = av.x;
        As[ak + 1][arow] = av.y;
        As[ak + 2][arow] = av.z;
        As[ak + 3][arow] = av.w;
        *(float4*)&Bs[brow][bc] = bv;
        __syncthreads();

#pragma unroll
        for (int k = 0; k < BK; k++) {
            // ra row-pairs come naturally packed from 16B loads
            ulonglong2 raA = *(const ulonglong2*)&As[k][ty * 4];       // {r0,r1},{r2,r3}
            ulonglong2 raB = *(const ulonglong2*)&As[k][64 + ty * 4];
            float4 b0 = *(const float4*)&Bs[k][tx * 4];
            float4 b1 = *(const float4*)&Bs[k][64 + tx * 4];
            unsigned long long rbd[8];
            PACKDUP(rbd[0], b0.x); PACKDUP(rbd[1], b0.y);
            PACKDUP(rbd[2], b0.z); PACKDUP(rbd[3], b0.w);
            PACKDUP(rbd[4], b1.x); PACKDUP(rbd[5], b1.y);
            PACKDUP(rbd[6], b1.z); PACKDUP(rbd[7], b1.w);
#pragma unroll
            for (int j = 0; j < 8; j++) {
                FMA2(acc2[0][j], raA.x, rbd[j]);
                FMA2(acc2[1][j], raA.y, rbd[j]);
                FMA2(acc2[2][j], raB.x, rbd[j]);
                FMA2(acc2[3][j], raB.y, rbd[j]);
            }
        }
        __syncthreads();
    }

    // epilogue: add bias, store to g_P
    float bvv[8];
#pragma unroll
    for (int j = 0; j < 4; j++) {
        bvv[j]     = bias[ncol0 + tx * 4 + j];
        bvv[4 + j] = bias[ncol0 + 64 + tx * 4 + j];
    }
#pragma unroll
    for (int ip = 0; ip < 4; ip++) {
        int rbase = (ip < 2) ? (ty * 4 + 2 * ip) : (64 + ty * 4 + 2 * (ip - 2));
#pragma unroll
        for (int half = 0; half < 2; half++) {
            int r = rbase + half;
            float v[8];
#pragma unroll
            for (int j = 0; j < 8; j++)
                v[j] = (half ? hi32(acc2[ip][j]) : lo32(acc2[ip][j])) + bvv[j];
            float* dst = g_P + (size_t)(m0 + r) * NG + n0;
            *(float4*)(dst + tx * 4)      = make_float4(v[0], v[1], v[2], v[3]);
            *(float4*)(dst + 64 + tx * 4) = make_float4(v[4], v[5], v[6], v[7]);
        }
    }
}

// ---------------- phase 2: clustered persistent recurrent kernel -----------
// 16 clusters (one per 4-row batch group) x 8 CTAs (32 d_h cols each).
// Thread = 1 gate-col x 4 batch rows: each Wh element read ONCE per step.
#define CLUSTER 8
#define NCLUS   (BATCH / 4)     // 16
#define NCTA2   (CLUSTER * NCLUS)
#define NTHR2   128
#define WPAD    260             // float stride: 16B-aligned, phase-conflict-free

struct S2 {
    float Wh[128][WPAD];        // [gatecol][k]  ~130 KB, resident all steps
    float hs[2][4][DH];         // double-buffered h(t): [buf][row][k]
    float gbuf[4][4][32];       // [gate][row][j] pre-activation exchange
};

__device__ __forceinline__ float fsig(float x) {
    return __fdividef(1.f, 1.f + __expf(-x));
}
__device__ __forceinline__ float ftanh(float x) {
    return __fdividef(2.f, 1.f + __expf(-2.f * x)) - 1.f;
}

extern __shared__ char smem_raw[];

__global__ __launch_bounds__(NTHR2, 1) __cluster_dims__(CLUSTER, 1, 1)
void lstm_rec_kernel(const float* __restrict__ Wf, const float* __restrict__ Wi,
                     const float* __restrict__ Wg, const float* __restrict__ Wo,
                     float* __restrict__ out, int out_size)
{
    S2* s = (S2*)smem_raw;
    int tid = threadIdx.x;
    uint32_t rank;
    asm("mov.u32 %0, %%cluster_ctarank;" : "=r"(rank));
    int d0 = (int)rank * 32;                 // my 32 d_h columns
    int b0 = (blockIdx.x >> 3) * 4;          // my 4 batch rows

    // ---- load this CTA's Wh slice: h-part rows of W, 4 gates x 32 cols
    for (int idx = tid; idx < 128 * 256; idx += NTHR2) {
        int c  = idx & 127;                  // gate-col 0..127
        int kk = idx >> 7;                   // k 0..255
        int gate = c >> 5;
        int j = d0 + (c & 31);
        const float* W = (gate == 0) ? Wf : (gate == 1) ? Wi : (gate == 2) ? Wg : Wo;
        s->Wh[c][kk] = W[(size_t)(DIN + kk) * DH + j];
    }
    // ---- zero local h buffer 0 (h(0) = 0)
    for (int idx = tid; idx < 4 * DH / 4; idx += NTHR2)
        ((float4*)s->hs[0])[idx] = make_float4(0.f, 0.f, 0.f, 0.f);
    __syncthreads();
    asm volatile("barrier.cluster.arrive.aligned;" ::: "memory");
    asm volatile("barrier.cluster.wait.aligned;"   ::: "memory");

    // ---- compute role: thread = gate-col c, all 4 rows
    int c  = tid;                            // 0..127
    int g0 = c >> 5, jj = c & 31;
    int gcol = (g0 << 8) + d0 + jj;          // global gate-column for P
    const ulonglong2* wp = (const ulonglong2*)s->Wh[c];

    // ---- activation role: thread = (row r2, dcol d0+j2)
    int r2 = tid >> 5, j2 = tid & 31;
    float c_reg = 0.f;

    // precompute remote DSMEM addresses of my h slot in both buffers
    uint32_t hsa0 = (uint32_t)__cvta_generic_to_shared(&s->hs[0][r2][d0 + j2]);
    uint32_t hsa1 = (uint32_t)__cvta_generic_to_shared(&s->hs[1][r2][d0 + j2]);
    uint32_t ra0[CLUSTER], ra1[CLUSTER];
#pragma unroll
    for (int p = 0; p < CLUSTER; p++) {
        asm("mapa.shared::cluster.u32 %0, %1, %2;" : "=r"(ra0[p]) : "r"(hsa0), "r"(p));
        asm("mapa.shared::cluster.u32 %0, %1, %2;" : "=r"(ra1[p]) : "r"(hsa1), "r"(p));
    }

    // P pointers: one per row (advance by BATCH*NG per step)
    const float* pP = g_P + (size_t)b0 * NG + gcol;
    float p0 = __ldcs(pP + 0 * NG);
    float p1 = __ldcs(pP + 1 * NG);
    float p2 = __ldcs(pP + 2 * NG);
    float p3 = __ldcs(pP + 3 * NG);

    float* orow = out + (size_t)(b0 + r2) * DH + d0 + j2;
    const size_t HOFF = (size_t)TT * BATCH * DH;

    for (int t = 0; t < TT; t++) {
        const ulonglong2* h0p = (const ulonglong2*)s->hs[t & 1][0];
        const ulonglong2* h1p = (const ulonglong2*)s->hs[t & 1][1];
        const ulonglong2* h2p = (const ulonglong2*)s->hs[t & 1][2];
        const ulonglong2* h3p = (const ulonglong2*)s->hs[t & 1][3];

        unsigned long long a0 = 0, a1 = 0, a2 = 0, a3 = 0;
#pragma unroll 8
        for (int i = 0; i < DH / 4; i++) {
            ulonglong2 w4 = wp[i];           // {w_k,w_k+1},{w_k+2,w_k+3}
            ulonglong2 h0 = h0p[i];
            ulonglong2 h1 = h1p[i];
            ulonglong2 h2 = h2p[i];
            ulonglong2 h3 = h3p[i];
            FMA2(a0, h0.x, w4.x); FMA2(a0, h0.y, w4.y);
            FMA2(a1, h1.x, w4.x); FMA2(a1, h1.y, w4.y);
            FMA2(a2, h2.x, w4.x); FMA2(a2, h2.y, w4.y);
            FMA2(a3, h3.x, w4.x); FMA2(a3, h3.y, w4.y);
        }
        s->gbuf[g0][0][jj] = pairsum(a0) + p0;
        s->gbuf[g0][1][jj] = pairsum(a1) + p1;
        s->gbuf[g0][2][jj] = pairsum(a2) + p2;
        s->gbuf[g0][3][jj] = pairsum(a3) + p3;
        __syncthreads();

        // activation: every thread owns one (row, dcol) cell
        float f  = fsig (s->gbuf[0][r2][j2]);
        float i_ = fsig (s->gbuf[1][r2][j2]);
        float g_ = ftanh(s->gbuf[2][r2][j2]);
        float o_ = fsig (s->gbuf[3][r2][j2]);
        c_reg = f * c_reg + i_ * g_;
        float hvn = o_ * ftanh(c_reg);

        // broadcast h(t+1) into every cluster CTA's hs[(t+1)&1]
        const uint32_t* ra = (t & 1) ? ra0 : ra1;
#pragma unroll
        for (int p = 0; p < CLUSTER; p++)
            asm volatile("st.shared::cluster.f32 [%0], %1;"
                         :: "r"(ra[p]), "f"(hvn) : "memory");

        // arrive FIRST (releases remote stores), then do independent work
        asm volatile("barrier.cluster.arrive.aligned;" ::: "memory");

        orow[(size_t)t * BATCH * DH] = hvn;
        if (t == TT - 1 &&
            HOFF + (size_t)2 * BATCH * DH <= (size_t)out_size) {
            out[HOFF + (size_t)(b0 + r2) * DH + d0 + j2] = hvn;
            out[HOFF + (size_t)BATCH * DH + (size_t)(b0 + r2) * DH + d0 + j2] = c_reg;
        }
        pP += (size_t)BATCH * NG;
        if (t + 1 < TT) {
            p0 = __ldcs(pP + 0 * NG);
            p1 = __ldcs(pP + 1 * NG);
            p2 = __ldcs(pP + 2 * NG);
            p3 = __ldcs(pP + 3 * NG);
        }

        asm volatile("barrier.cluster.wait.aligned;" ::: "memory");
    }
}

// ---------------- launch ---------------------------------------------------
extern "C" void kernel_launch(void* const* d_in, const int* in_sizes, int n_in,
                              void* d_out, int out_size)
{
    const float* X  = (const float*)d_in[0];
    const float* Wf = (const float*)d_in[1];
    const float* bf = (const float*)d_in[2];
    const float* Wi = (const float*)d_in[3];
    const float* bi = (const float*)d_in[4];
    const float* Wg = (const float*)d_in[5];
    const float* bg = (const float*)d_in[6];
    const float* Wo = (const float*)d_in[7];
    const float* bo = (const float*)d_in[8];
    float* out = (float*)d_out;

    // phase 1: big parallel GEMM for the x-projection of all timesteps
    dim3 g1(NG / 128, (TT * BATCH) / 128);
    gemm_x_kernel<<<g1, 256>>>(X, Wf, Wi, Wg, Wo, bf, bi, bg, bo);

    // phase 2: 16 clusters x 8 CTAs, DSMEM h-exchange
    cudaFuncSetAttribute(lstm_rec_kernel,
                         cudaFuncAttributeMaxDynamicSharedMemorySize,
                         (int)sizeof(S2));
    lstm_rec_kernel<<<NCTA2, NTHR2, sizeof(S2)>>>(Wf, Wi, Wg, Wo, out, out_size);
}